// round 14
// baseline (speedup 1.0000x reference)
#include <cuda_runtime.h>
#include <math.h>

#define Bq 16
#define Gq 32
#define Tq 4096
#define Dq 512
#define Kq 8
#define BG (Bq*Gq)          // 512
#define NWIN (Tq-3)         // 4093
#define NPAIR (NWIN-1)      // 4092
#define MPq 24
#define BINS 576
#define HSTRIDE 577         // bank-staggered histogram copy stride

// ---------------- tables + scratch ----------------
__device__ float2 g_filt2[4*Tq];              // packed filter pairs, base-8 digit-reversed, /4096 folded
__device__ float2 g_tw[512];                  // exp(-2*pi*i*m/4096), m<512
__device__ int    g_lut[64];
__device__ float  g_pooled[(size_t)BG*Tq];    // 8 MB
__device__ float2 g_spec[(size_t)BG*Tq];      // 16 MB spectrum (physical layout)
__device__ float  g_modes[(size_t)BG*Kq*Tq + 16]; // 64 MB modes

// ---------------- helpers ----------------
__device__ __forceinline__ int swb(int e){ return e ^ ((e >> 4) & 7) ^ (((e >> 6) & 1) << 3); }
__device__ __forceinline__ int swt(int m){ return m ^ ((m >> 4) & 15); }
__device__ __forceinline__ float2 cadd(float2 a, float2 b){ return make_float2(a.x+b.x, a.y+b.y); }
__device__ __forceinline__ float2 csub(float2 a, float2 b){ return make_float2(a.x-b.x, a.y-b.y); }
__device__ __forceinline__ float2 cmul(float2 a, float2 b){ return make_float2(a.x*b.x - a.y*b.y, a.x*b.y + a.y*b.x); }
__device__ __forceinline__ float2 cmulc(float2 a, float2 b){ return make_float2(a.x*b.x + a.y*b.y, a.y*b.x - a.x*b.y); }

#define CSQ2 0.70710678118654752440f

__device__ __forceinline__ void dft8_fwd(float2* x) {
    float2 t0 = cadd(x[0], x[4]), t1 = csub(x[0], x[4]);
    float2 t2 = cadd(x[2], x[6]), t3 = csub(x[2], x[6]);
    float2 s0 = cadd(x[1], x[5]), s1 = csub(x[1], x[5]);
    float2 s2 = cadd(x[3], x[7]), s3 = csub(x[3], x[7]);
    float2 E0 = cadd(t0, t2), E2 = csub(t0, t2);
    float2 E1 = make_float2(t1.x + t3.y, t1.y - t3.x);
    float2 E3 = make_float2(t1.x - t3.y, t1.y + t3.x);
    float2 O0 = cadd(s0, s2), Oq = csub(s0, s2);
    float2 O1 = make_float2(s1.x + s3.y, s1.y - s3.x);
    float2 O3 = make_float2(s1.x - s3.y, s1.y + s3.x);
    float2 u1 = make_float2(CSQ2*(O1.x + O1.y), CSQ2*(O1.y - O1.x));
    float2 u2 = make_float2(Oq.y, -Oq.x);
    float2 u3 = make_float2(CSQ2*(O3.y - O3.x), -CSQ2*(O3.x + O3.y));
    x[0] = cadd(E0, O0); x[4] = csub(E0, O0);
    x[1] = cadd(E1, u1); x[5] = csub(E1, u1);
    x[2] = cadd(E2, u2); x[6] = csub(E2, u2);
    x[3] = cadd(E3, u3); x[7] = csub(E3, u3);
}

__device__ __forceinline__ void dft8_inv(float2* x) {
    float2 t0 = cadd(x[0], x[4]), t1 = csub(x[0], x[4]);
    float2 t2 = cadd(x[2], x[6]), t3 = csub(x[2], x[6]);
    float2 s0 = cadd(x[1], x[5]), s1 = csub(x[1], x[5]);
    float2 s2 = cadd(x[3], x[7]), s3 = csub(x[3], x[7]);
    float2 E0 = cadd(t0, t2), E2 = csub(t0, t2);
    float2 E1 = make_float2(t1.x - t3.y, t1.y + t3.x);
    float2 E3 = make_float2(t1.x + t3.y, t1.y - t3.x);
    float2 O0 = cadd(s0, s2), Oq = csub(s0, s2);
    float2 O1 = make_float2(s1.x - s3.y, s1.y + s3.x);
    float2 O3 = make_float2(s1.x + s3.y, s1.y - s3.x);
    float2 u1 = make_float2(CSQ2*(O1.x - O1.y), CSQ2*(O1.x + O1.y));
    float2 u2 = make_float2(-Oq.y, Oq.x);
    float2 u3 = make_float2(-CSQ2*(O3.x + O3.y), CSQ2*(O3.x - O3.y));
    x[0] = cadd(E0, O0); x[4] = csub(E0, O0);
    x[1] = cadd(E1, u1); x[5] = csub(E1, u1);
    x[2] = cadd(E2, u2); x[6] = csub(E2, u2);
    x[3] = cadd(E3, u3); x[7] = csub(E3, u3);
}

// ---------------- init work (device function, run by first 16 blocks of pool launch) ----------------
__device__ double filt_val(int idx, double cf) {
    double fr = (idx < Tq/2) ? (double)idx / Tq : (double)(idx - Tq) / Tq;
    double d = fabs(fr - cf) / 0.125;
    return exp(-0.5 * d * d);
}

__device__ void init_work(int blk, int tid) {
    int j = blk * 256 + tid;                 // 0..4095
    if (j < 512) {
        float a = -(float)j / 2048.0f;
        g_tw[j] = make_float2(cospif(a), sinpif(a));
    }
    {
        int f = ((j & 7) << 9) | (((j >> 3) & 7) << 6) | (((j >> 6) & 7) << 3) | ((j >> 9) & 7);
        int fc = (Tq - f) & (Tq - 1);
        #pragma unroll
        for (int p = 0; p < 4; p++) {
            double cf0 = -0.5 + (double)(2*p)   / 7.0;
            double cf1 = -0.5 + (double)(2*p+1) / 7.0;
            double g0 = 0.5 * (filt_val(f, cf0) + filt_val(fc, cf0)) / (double)Tq;
            double g1 = 0.5 * (filt_val(f, cf1) + filt_val(fc, cf1)) / (double)Tq;
            g_filt2[p*Tq + j] = make_float2((float)g0, (float)g1);
        }
    }
    if (j == 0) {
        for (int q = 0; q < 64; q++) g_lut[q] = 0;
        for (int r0 = 0; r0 < 4; r0++)
        for (int r1 = 0; r1 < 4; r1++) { if (r1 == r0) continue;
        for (int r2 = 0; r2 < 4; r2++) { if (r2 == r0 || r2 == r1) continue;
            int r3 = 6 - r0 - r1 - r2;
            int rk[4] = {r0, r1, r2, r3};
            int si[4];
            for (int i = 0; i < 4; i++) si[rk[i]] = i;
            // key layout: bit0=b01, bit1=b12, bit2=b23, bit3=b02, bit4=b13, bit5=b03
            int key = (rk[0]>rk[1]) | ((rk[1]>rk[2])<<1) | ((rk[2]>rk[3])<<2)
                    | ((rk[0]>rk[2])<<3) | ((rk[1]>rk[3])<<4) | ((rk[0]>rk[3])<<5);
            int c0 = (si[0]>si[1]) + (si[0]>si[2]) + (si[0]>si[3]);
            int c1 = (si[1]>si[2]) + (si[1]>si[3]);
            int c2 = (si[2]>si[3]);
            g_lut[key] = 6*c0 + 2*c1 + c2;
        }}
    }
}

// ---------------- kernel P: init blocks + coalesced pooling ----------------
__global__ void __launch_bounds__(256) pool_kernel(const float* __restrict__ hs) {
    if (blockIdx.x < 16) { init_work(blockIdx.x, threadIdx.x); return; }
    __shared__ float sm[64][33];
    const int bid = blockIdx.x - 16;
    const int b  = bid >> 6;
    const int t0 = (bid & 63) * 64;
    const int wid = threadIdx.x >> 5, lane = threadIdx.x & 31;
    #pragma unroll
    for (int rr = 0; rr < 8; rr++) {
        int tr = wid * 8 + rr;
        const float4* row = (const float4*)(hs + ((size_t)b * Tq + t0 + tr) * Dq);
        #pragma unroll
        for (int pass = 0; pass < 4; pass++) {
            float4 v = row[pass*32 + lane];
            float s = v.x + v.y + v.z + v.w;
            s += __shfl_xor_sync(0xffffffffu, s, 1);
            s += __shfl_xor_sync(0xffffffffu, s, 2);
            if ((lane & 3) == 0) sm[tr][pass*8 + (lane >> 2)] = s * (1.0f/16.0f);
        }
    }
    __syncthreads();
    for (int i = threadIdx.x; i < 32*64; i += 256) {
        int g = i >> 6, tr = i & 63;
        g_pooled[((size_t)b * Gq + g) * Tq + t0 + tr] = sm[tr][g];
    }
}

#define DSM ((Tq + 512) * 8)   // buf 4096 float2 + stw 512 float2 = 36 KB

// ---------------- kernel A: forward radix-8 FFT, global->regs->smem->...->global ----------------
__global__ void __launch_bounds__(512, 3) fwd_kernel() {
    cudaGridDependencySynchronize();   // PDL: wait for pool_kernel completion
    extern __shared__ float2 sh[];
    float2* buf = sh;
    float2* stw = sh + Tq;
    const int u = threadIdx.x;
    const int bg = blockIdx.x;

    stw[swt(u)] = g_tw[u];
    const float* pooled = g_pooled + (size_t)bg * Tq;

    // stage 0 (h=512): coalesced global loads straight into registers
    {
        float2 x[8];
        #pragma unroll
        for (int c = 0; c < 8; c++) x[c] = make_float2(pooled[u + 512*c], 0.0f);
        dft8_fwd(x);
        float2 w1 = stw[swt(u)];
        float2 w2 = cmul(w1, w1), w3 = cmul(w2, w1), w4 = cmul(w2, w2);
        float2 w5 = cmul(w3, w2), w6 = cmul(w3, w3), w7 = cmul(w4, w3);
        x[1] = cmul(x[1], w1); x[2] = cmul(x[2], w2); x[3] = cmul(x[3], w3);
        x[4] = cmul(x[4], w4); x[5] = cmul(x[5], w5); x[6] = cmul(x[6], w6);
        x[7] = cmul(x[7], w7);
        #pragma unroll
        for (int c = 0; c < 8; c++) buf[swb(u + 512*c)] = x[c];
        __syncthreads();
    }

    // stages 1,2: shared memory
    #pragma unroll
    for (int s = 1; s < 3; s++) {
        const int h  = 512 >> (3*s);     // 64, 8
        const int tm = 1 << (3*s);
        int j = u & (h - 1);
        int i = ((u ^ j) << 3) | j;
        float2 x[8];
        #pragma unroll
        for (int c = 0; c < 8; c++) x[c] = buf[swb(i + c*h)];
        dft8_fwd(x);
        int m = j * tm;
        float2 w1 = stw[swt(m)];
        float2 w2 = cmul(w1, w1), w3 = cmul(w2, w1), w4 = cmul(w2, w2);
        float2 w5 = cmul(w3, w2), w6 = cmul(w3, w3), w7 = cmul(w4, w3);
        x[1] = cmul(x[1], w1); x[2] = cmul(x[2], w2); x[3] = cmul(x[3], w3);
        x[4] = cmul(x[4], w4); x[5] = cmul(x[5], w5); x[6] = cmul(x[6], w6);
        x[7] = cmul(x[7], w7);
        #pragma unroll
        for (int c = 0; c < 8; c++) buf[swb(i + c*h)] = x[c];
        __syncthreads();
    }

    // stage 3 (h=1): smem -> regs -> direct global store
    {
        float2 x[8];
        #pragma unroll
        for (int c = 0; c < 8; c++) x[c] = buf[swb(8*u + c)];
        dft8_fwd(x);
        float2* dst = g_spec + (size_t)bg * Tq;
        #pragma unroll
        for (int c = 0; c < 8; c++) dst[swb(8*u + c)] = x[c];
    }
}

// ---------------- kernel B: filter + inverse FFT, TWO pairs per block -> g_modes ----------------
__global__ void __launch_bounds__(512, 3) ifft_kernel() {
    cudaGridDependencySynchronize();   // PDL: wait for fwd_kernel completion
    extern __shared__ float2 sh[];
    float2* W   = sh;
    float2* stw = sh + Tq;
    const int bg = blockIdx.x >> 1;
    const int q  = blockIdx.x & 1;
    const int u  = threadIdx.x;

    stw[swt(u)] = g_tw[u];
    const float2* Xg = g_spec + (size_t)bg * Tq;

    #pragma unroll
    for (int p2 = 0; p2 < 2; p2++) {
        const int p = q * 2 + p2;
        const float2* fp = g_filt2 + p * Tq;

        // stage 0 (h=1): load spectrum + filter straight from global (2nd pass hits L1/L2)
        {
            float2 x[8];
            #pragma unroll
            for (int c = 0; c < 8; c++) {
                int e = 8*u + c;
                float2 xs = Xg[swb(e)];
                float2 f  = fp[e];
                x[c] = make_float2(xs.x*f.x - xs.y*f.y, xs.x*f.y + xs.y*f.x);
            }
            dft8_inv(x);
            #pragma unroll
            for (int c = 0; c < 8; c++) W[swb(8*u + c)] = x[c];
            __syncthreads();
        }

        // stages 1,2: shared memory
        #pragma unroll
        for (int s = 1; s < 3; s++) {
            const int h  = 1 << (3*s);       // 8, 64
            const int tm = 512 >> (3*s);
            int j = u & (h - 1);
            int i = ((u ^ j) << 3) | j;
            float2 x[8];
            #pragma unroll
            for (int c = 0; c < 8; c++) x[c] = W[swb(i + c*h)];
            int m = j * tm;
            float2 w1 = stw[swt(m)];
            float2 w2 = cmul(w1, w1), w3 = cmul(w2, w1), w4 = cmul(w2, w2);
            float2 w5 = cmul(w3, w2), w6 = cmul(w3, w3), w7 = cmul(w4, w3);
            x[1] = cmulc(x[1], w1); x[2] = cmulc(x[2], w2); x[3] = cmulc(x[3], w3);
            x[4] = cmulc(x[4], w4); x[5] = cmulc(x[5], w5); x[6] = cmulc(x[6], w6);
            x[7] = cmulc(x[7], w7);
            dft8_inv(x);
            #pragma unroll
            for (int c = 0; c < 8; c++) W[swb(i + c*h)] = x[c];
            __syncthreads();
        }

        // stage 3 (h=512): smem -> regs -> coalesced global stores
        {
            float2 x[8];
            #pragma unroll
            for (int c = 0; c < 8; c++) x[c] = W[swb(u + c*512)];
            float2 w1 = stw[swt(u)];
            float2 w2 = cmul(w1, w1), w3 = cmul(w2, w1), w4 = cmul(w2, w2);
            float2 w5 = cmul(w3, w2), w6 = cmul(w3, w3), w7 = cmul(w4, w3);
            x[1] = cmulc(x[1], w1); x[2] = cmulc(x[2], w2); x[3] = cmulc(x[3], w3);
            x[4] = cmulc(x[4], w4); x[5] = cmulc(x[5], w5); x[6] = cmulc(x[6], w6);
            x[7] = cmulc(x[7], w7);
            dft8_inv(x);
            float* mo0 = g_modes + ((size_t)bg * Kq + 2*p)     * Tq;
            float* mo1 = g_modes + ((size_t)bg * Kq + 2*p + 1) * Tq;
            #pragma unroll
            for (int c = 0; c < 8; c++) {
                mo0[u + 512*c] = x[c].x;
                mo1[u + 512*c] = x[c].y;
            }
        }
        __syncthreads();   // protect W reuse across pair iterations
    }
}

// ---------------- kernel T: tmptm, one block per bg; early PDL trigger for momfinal overlap ----------------
__global__ void __launch_bounds__(512, 4) tmptm_kernel(float* __restrict__ out) {
    cudaGridDependencySynchronize();             // wait for ifft_kernel completion
    cudaTriggerProgrammaticLaunchCompletion();   // let momfinal launch & run concurrently
    __shared__ int hist[8*HSTRIDE];
    __shared__ int lut[64];
    const int bg  = blockIdx.x;
    const int tid = threadIdx.x;
    for (int i = tid; i < 8*HSTRIDE; i += 512) hist[i] = 0;
    if (tid < 64) lut[tid] = g_lut[tid];
    __syncthreads();

    int* myhist = hist + (tid & 7) * HSTRIDE;
    const int n0 = tid * 8;

    for (int k = 0; k < Kq; k++) {
        const float4* r4 = (const float4*)(g_modes + ((size_t)bg * Kq + k) * Tq + n0);
        float4 a = r4[0], b = r4[1], c = r4[2];
        // key layout: bit0=b01, bit1=b12, bit2=b23, bit3=b02, bit4=b13, bit5=b03
        int key = (a.x>a.y) | ((a.y>a.z)<<1) | ((a.z>a.w)<<2)
                | ((a.x>a.z)<<3) | ((a.y>a.w)<<4) | ((a.x>a.w)<<5);
        int prev = lut[key];
        float w1 = a.y, w2 = a.z, w3 = a.w;
        int lastLin = -1, cnt = 0;
        #define STEP(v, ii) { \
            key = ((key>>1) & 11) | ((w3>(v))<<2) | ((w2>(v))<<4) | ((w1>(v))<<5); \
            int cur = lut[key]; \
            if ((n0 + (ii)) < NPAIR) { \
                int lin = prev*MPq + cur; \
                if (lin == lastLin) cnt++; \
                else { if (cnt) atomicAdd(&myhist[lastLin], cnt); lastLin = lin; cnt = 1; } \
            } \
            prev = cur; w1 = w2; w2 = w3; w3 = (v); }
        STEP(b.x, 0) STEP(b.y, 1) STEP(b.z, 2) STEP(b.w, 3)
        STEP(c.x, 4) STEP(c.y, 5) STEP(c.z, 6) STEP(c.w, 7)
        #undef STEP
        if (cnt) atomicAdd(&myhist[lastLin], cnt);
    }
    __syncthreads();

    const float invs = 1.0f / (float)(Kq * NPAIR);
    for (int i = tid; i < BINS; i += 512) {
        int s = 0;
        #pragma unroll
        for (int c = 0; c < 8; c++) s += hist[c*HSTRIDE + i];
        out[(size_t)bg * BINS + i] = (float)s * invs;
    }
}

// ---------------- kernel M: moments + fmptm (runs concurrently with tmptm) ----------------
__global__ void __launch_bounds__(256) momfinal_kernel(float* __restrict__ out) {
    cudaGridDependencySynchronize();   // PDL: waits only for tmptm's early trigger (ifft already complete)
    const int bg = blockIdx.x, tid = threadIdx.x;
    const float4* base = (const float4*)(g_modes + (size_t)bg * Kq * Tq);
    float s1[Kq]; float s2[36];
    #pragma unroll
    for (int i = 0; i < Kq; i++) s1[i] = 0.0f;
    #pragma unroll
    for (int i = 0; i < 36; i++) s2[i] = 0.0f;

    #pragma unroll
    for (int it = 0; it < 4; it++) {
        const int idx4 = it * 256 + tid;
        float4 E[Kq];
        #pragma unroll
        for (int k = 0; k < Kq; k++) {
            float4 v = base[k * (Tq/4) + idx4];
            E[k] = make_float4(v.x*v.x, v.y*v.y, v.z*v.z, v.w*v.w);
        }
        #pragma unroll
        for (int k = 0; k < Kq; k++) s1[k] += E[k].x + E[k].y + E[k].z + E[k].w;
        int idx = 0;
        #pragma unroll
        for (int k = 0; k < Kq; k++)
            #pragma unroll
            for (int l = k; l < Kq; l++)
                s2[idx++] += E[k].x*E[l].x + E[k].y*E[l].y + E[k].z*E[l].z + E[k].w*E[l].w;
    }

    __shared__ float red[44];
    if (tid < 44) red[tid] = 0.0f;
    __syncthreads();
    #pragma unroll
    for (int i = 0; i < Kq; i++) {
        float v = s1[i];
        #pragma unroll
        for (int o = 16; o; o >>= 1) v += __shfl_down_sync(0xffffffffu, v, o);
        if ((tid & 31) == 0) atomicAdd(&red[i], v);
    }
    #pragma unroll
    for (int i = 0; i < 36; i++) {
        float v = s2[i];
        #pragma unroll
        for (int o = 16; o; o >>= 1) v += __shfl_down_sync(0xffffffffu, v, o);
        if ((tid & 31) == 0) atomicAdd(&red[8 + i], v);
    }
    __syncthreads();

    if (tid < 28) {
        float* out2 = out + (size_t)BG * BINS;
        int k = 0, rem = tid;
        while (rem >= 7 - k) { rem -= 7 - k; k++; }
        int l = k + 1 + rem;
        float S1k = red[k], S1l = red[l];
        int dk = 8 + (k * (17 - k)) / 2;
        int dl = 8 + (l * (17 - l)) / 2;
        float S2kk = red[dk], S2ll = red[dl];
        int off = k * 8 - (k * (k - 1)) / 2 + (l - k);
        float S2kl = red[8 + off];
        const float Tf = (float)Tq;
        float vk = (S2kk - S1k * S1k / Tf) / (Tf - 1.0f);
        float vl = (S2ll - S1l * S1l / Tf) / (Tf - 1.0f);
        float sk = fmaxf(sqrtf(fmaxf(vk, 0.0f)), 1e-8f);
        float sl = fmaxf(sqrtf(fmaxf(vl, 0.0f)), 1e-8f);
        float corr = (S2kl - S1k * S1l / Tf) / (Tf * sk * sl);
        out2[(size_t)bg * 28 + tid] = corr;
    }
}

// ---------------- launch (PDL chaining) ----------------
template <typename... Args, typename F>
static inline void launch_pdl(F func, dim3 grid, dim3 block, size_t smem, Args... args) {
    cudaLaunchConfig_t cfg = {};
    cfg.gridDim = grid;
    cfg.blockDim = block;
    cfg.dynamicSmemBytes = smem;
    cfg.stream = 0;
    cudaLaunchAttribute attr[1];
    attr[0].id = cudaLaunchAttributeProgrammaticStreamSerialization;
    attr[0].val.programmaticStreamSerializationAllowed = 1;
    cfg.attrs = attr;
    cfg.numAttrs = 1;
    cudaLaunchKernelEx(&cfg, func, args...);
}

extern "C" void kernel_launch(void* const* d_in, const int* in_sizes, int n_in,
                              void* d_out, int out_size) {
    const float* hs = (const float*)d_in[0];
    float* out = (float*)d_out;

    cudaFuncSetAttribute(fwd_kernel,  cudaFuncAttributeMaxDynamicSharedMemorySize, DSM);
    cudaFuncSetAttribute(ifft_kernel, cudaFuncAttributeMaxDynamicSharedMemorySize, DSM);

    pool_kernel<<<Bq*64 + 16, 256>>>(hs);
    launch_pdl(fwd_kernel,      dim3(BG),   dim3(512), (size_t)DSM);
    launch_pdl(ifft_kernel,     dim3(BG*2), dim3(512), (size_t)DSM);
    launch_pdl(tmptm_kernel,    dim3(BG),   dim3(512), (size_t)0, out);
    launch_pdl(momfinal_kernel, dim3(BG),   dim3(256), (size_t)0, out);
}

// round 15
// speedup vs baseline: 1.0984x; 1.0984x over previous
#include <cuda_runtime.h>
#include <math.h>

#define Bq 16
#define Gq 32
#define Tq 4096
#define Dq 512
#define Kq 8
#define BG (Bq*Gq)          // 512
#define NWIN (Tq-3)         // 4093
#define NPAIR (NWIN-1)      // 4092
#define MPq 24
#define BINS 576
#define HSTRIDE 577         // bank-staggered histogram copy stride

// ---------------- tables + scratch ----------------
__device__ float2 g_filt2[4*Tq];              // packed filter pairs, base-8 digit-reversed, /4096 folded
__device__ float2 g_tw[512];                  // exp(-2*pi*i*m/4096), m<512
__device__ int    g_lut[64];
__device__ float  g_pooled[(size_t)BG*Tq];    // 8 MB
__device__ float2 g_spec[(size_t)BG*Tq];      // 16 MB spectrum (physical layout)
__device__ float  g_modes[(size_t)BG*Kq*Tq + 16]; // 64 MB modes

// ---------------- helpers ----------------
__device__ __forceinline__ int swb(int e){ return e ^ ((e >> 4) & 7) ^ (((e >> 6) & 1) << 3); }
__device__ __forceinline__ int swt(int m){ return m ^ ((m >> 4) & 15); }
__device__ __forceinline__ float2 cadd(float2 a, float2 b){ return make_float2(a.x+b.x, a.y+b.y); }
__device__ __forceinline__ float2 csub(float2 a, float2 b){ return make_float2(a.x-b.x, a.y-b.y); }
__device__ __forceinline__ float2 cmul(float2 a, float2 b){ return make_float2(a.x*b.x - a.y*b.y, a.x*b.y + a.y*b.x); }
__device__ __forceinline__ float2 cmulc(float2 a, float2 b){ return make_float2(a.x*b.x + a.y*b.y, a.y*b.x - a.x*b.y); }

#define CSQ2 0.70710678118654752440f

__device__ __forceinline__ void dft8_fwd(float2* x) {
    float2 t0 = cadd(x[0], x[4]), t1 = csub(x[0], x[4]);
    float2 t2 = cadd(x[2], x[6]), t3 = csub(x[2], x[6]);
    float2 s0 = cadd(x[1], x[5]), s1 = csub(x[1], x[5]);
    float2 s2 = cadd(x[3], x[7]), s3 = csub(x[3], x[7]);
    float2 E0 = cadd(t0, t2), E2 = csub(t0, t2);
    float2 E1 = make_float2(t1.x + t3.y, t1.y - t3.x);
    float2 E3 = make_float2(t1.x - t3.y, t1.y + t3.x);
    float2 O0 = cadd(s0, s2), Oq = csub(s0, s2);
    float2 O1 = make_float2(s1.x + s3.y, s1.y - s3.x);
    float2 O3 = make_float2(s1.x - s3.y, s1.y + s3.x);
    float2 u1 = make_float2(CSQ2*(O1.x + O1.y), CSQ2*(O1.y - O1.x));
    float2 u2 = make_float2(Oq.y, -Oq.x);
    float2 u3 = make_float2(CSQ2*(O3.y - O3.x), -CSQ2*(O3.x + O3.y));
    x[0] = cadd(E0, O0); x[4] = csub(E0, O0);
    x[1] = cadd(E1, u1); x[5] = csub(E1, u1);
    x[2] = cadd(E2, u2); x[6] = csub(E2, u2);
    x[3] = cadd(E3, u3); x[7] = csub(E3, u3);
}

__device__ __forceinline__ void dft8_inv(float2* x) {
    float2 t0 = cadd(x[0], x[4]), t1 = csub(x[0], x[4]);
    float2 t2 = cadd(x[2], x[6]), t3 = csub(x[2], x[6]);
    float2 s0 = cadd(x[1], x[5]), s1 = csub(x[1], x[5]);
    float2 s2 = cadd(x[3], x[7]), s3 = csub(x[3], x[7]);
    float2 E0 = cadd(t0, t2), E2 = csub(t0, t2);
    float2 E1 = make_float2(t1.x - t3.y, t1.y + t3.x);
    float2 E3 = make_float2(t1.x + t3.y, t1.y - t3.x);
    float2 O0 = cadd(s0, s2), Oq = csub(s0, s2);
    float2 O1 = make_float2(s1.x - s3.y, s1.y + s3.x);
    float2 O3 = make_float2(s1.x + s3.y, s1.y - s3.x);
    float2 u1 = make_float2(CSQ2*(O1.x - O1.y), CSQ2*(O1.x + O1.y));
    float2 u2 = make_float2(-Oq.y, Oq.x);
    float2 u3 = make_float2(-CSQ2*(O3.x + O3.y), CSQ2*(O3.x - O3.y));
    x[0] = cadd(E0, O0); x[4] = csub(E0, O0);
    x[1] = cadd(E1, u1); x[5] = csub(E1, u1);
    x[2] = cadd(E2, u2); x[6] = csub(E2, u2);
    x[3] = cadd(E3, u3); x[7] = csub(E3, u3);
}

// ---------------- init work (device function, run by first 16 blocks of pool launch) ----------------
__device__ double filt_val(int idx, double cf) {
    double fr = (idx < Tq/2) ? (double)idx / Tq : (double)(idx - Tq) / Tq;
    double d = fabs(fr - cf) / 0.125;
    return exp(-0.5 * d * d);
}

__device__ void init_work(int blk, int tid) {
    int j = blk * 256 + tid;                 // 0..4095
    if (j < 512) {
        float a = -(float)j / 2048.0f;
        g_tw[j] = make_float2(cospif(a), sinpif(a));
    }
    {
        int f = ((j & 7) << 9) | (((j >> 3) & 7) << 6) | (((j >> 6) & 7) << 3) | ((j >> 9) & 7);
        int fc = (Tq - f) & (Tq - 1);
        #pragma unroll
        for (int p = 0; p < 4; p++) {
            double cf0 = -0.5 + (double)(2*p)   / 7.0;
            double cf1 = -0.5 + (double)(2*p+1) / 7.0;
            double g0 = 0.5 * (filt_val(f, cf0) + filt_val(fc, cf0)) / (double)Tq;
            double g1 = 0.5 * (filt_val(f, cf1) + filt_val(fc, cf1)) / (double)Tq;
            g_filt2[p*Tq + j] = make_float2((float)g0, (float)g1);
        }
    }
    if (j == 0) {
        for (int q = 0; q < 64; q++) g_lut[q] = 0;
        for (int r0 = 0; r0 < 4; r0++)
        for (int r1 = 0; r1 < 4; r1++) { if (r1 == r0) continue;
        for (int r2 = 0; r2 < 4; r2++) { if (r2 == r0 || r2 == r1) continue;
            int r3 = 6 - r0 - r1 - r2;
            int rk[4] = {r0, r1, r2, r3};
            int si[4];
            for (int i = 0; i < 4; i++) si[rk[i]] = i;
            // key layout: bit0=b01, bit1=b12, bit2=b23, bit3=b02, bit4=b13, bit5=b03
            int key = (rk[0]>rk[1]) | ((rk[1]>rk[2])<<1) | ((rk[2]>rk[3])<<2)
                    | ((rk[0]>rk[2])<<3) | ((rk[1]>rk[3])<<4) | ((rk[0]>rk[3])<<5);
            int c0 = (si[0]>si[1]) + (si[0]>si[2]) + (si[0]>si[3]);
            int c1 = (si[1]>si[2]) + (si[1]>si[3]);
            int c2 = (si[2]>si[3]);
            g_lut[key] = 6*c0 + 2*c1 + c2;
        }}
    }
}

// ---------------- kernel P: init blocks + coalesced pooling ----------------
__global__ void __launch_bounds__(256) pool_kernel(const float* __restrict__ hs) {
    if (blockIdx.x < 16) { init_work(blockIdx.x, threadIdx.x); return; }
    __shared__ float sm[64][33];
    const int bid = blockIdx.x - 16;
    const int b  = bid >> 6;
    const int t0 = (bid & 63) * 64;
    const int wid = threadIdx.x >> 5, lane = threadIdx.x & 31;
    #pragma unroll
    for (int rr = 0; rr < 8; rr++) {
        int tr = wid * 8 + rr;
        const float4* row = (const float4*)(hs + ((size_t)b * Tq + t0 + tr) * Dq);
        #pragma unroll
        for (int pass = 0; pass < 4; pass++) {
            float4 v = row[pass*32 + lane];
            float s = v.x + v.y + v.z + v.w;
            s += __shfl_xor_sync(0xffffffffu, s, 1);
            s += __shfl_xor_sync(0xffffffffu, s, 2);
            if ((lane & 3) == 0) sm[tr][pass*8 + (lane >> 2)] = s * (1.0f/16.0f);
        }
    }
    __syncthreads();
    for (int i = threadIdx.x; i < 32*64; i += 256) {
        int g = i >> 6, tr = i & 63;
        g_pooled[((size_t)b * Gq + g) * Tq + t0 + tr] = sm[tr][g];
    }
}

#define DSM ((Tq + 512) * 8)   // buf 4096 float2 + stw 512 float2 = 36 KB

// ---------------- kernel A: forward radix-8 FFT, global->regs->smem->...->global ----------------
__global__ void __launch_bounds__(512, 3) fwd_kernel() {
    cudaGridDependencySynchronize();   // PDL: wait for pool_kernel completion
    extern __shared__ float2 sh[];
    float2* buf = sh;
    float2* stw = sh + Tq;
    const int u = threadIdx.x;
    const int bg = blockIdx.x;

    stw[swt(u)] = g_tw[u];
    const float* pooled = g_pooled + (size_t)bg * Tq;

    // stage 0 (h=512): coalesced global loads straight into registers
    {
        float2 x[8];
        #pragma unroll
        for (int c = 0; c < 8; c++) x[c] = make_float2(pooled[u + 512*c], 0.0f);
        dft8_fwd(x);
        float2 w1 = stw[swt(u)];
        float2 w2 = cmul(w1, w1), w3 = cmul(w2, w1), w4 = cmul(w2, w2);
        float2 w5 = cmul(w3, w2), w6 = cmul(w3, w3), w7 = cmul(w4, w3);
        x[1] = cmul(x[1], w1); x[2] = cmul(x[2], w2); x[3] = cmul(x[3], w3);
        x[4] = cmul(x[4], w4); x[5] = cmul(x[5], w5); x[6] = cmul(x[6], w6);
        x[7] = cmul(x[7], w7);
        #pragma unroll
        for (int c = 0; c < 8; c++) buf[swb(u + 512*c)] = x[c];
        __syncthreads();
    }

    // stages 1,2: shared memory
    #pragma unroll
    for (int s = 1; s < 3; s++) {
        const int h  = 512 >> (3*s);     // 64, 8
        const int tm = 1 << (3*s);
        int j = u & (h - 1);
        int i = ((u ^ j) << 3) | j;
        float2 x[8];
        #pragma unroll
        for (int c = 0; c < 8; c++) x[c] = buf[swb(i + c*h)];
        dft8_fwd(x);
        int m = j * tm;
        float2 w1 = stw[swt(m)];
        float2 w2 = cmul(w1, w1), w3 = cmul(w2, w1), w4 = cmul(w2, w2);
        float2 w5 = cmul(w3, w2), w6 = cmul(w3, w3), w7 = cmul(w4, w3);
        x[1] = cmul(x[1], w1); x[2] = cmul(x[2], w2); x[3] = cmul(x[3], w3);
        x[4] = cmul(x[4], w4); x[5] = cmul(x[5], w5); x[6] = cmul(x[6], w6);
        x[7] = cmul(x[7], w7);
        #pragma unroll
        for (int c = 0; c < 8; c++) buf[swb(i + c*h)] = x[c];
        __syncthreads();
    }

    // stage 3 (h=1): smem -> regs -> direct global store
    {
        float2 x[8];
        #pragma unroll
        for (int c = 0; c < 8; c++) x[c] = buf[swb(8*u + c)];
        dft8_fwd(x);
        float2* dst = g_spec + (size_t)bg * Tq;
        #pragma unroll
        for (int c = 0; c < 8; c++) dst[swb(8*u + c)] = x[c];
    }
}

// ---------------- kernel B: filter (fused into stage 0) + inverse FFT -> g_modes ----------------
__global__ void __launch_bounds__(512, 3) ifft_kernel() {
    cudaGridDependencySynchronize();   // PDL: wait for fwd_kernel completion
    extern __shared__ float2 sh[];
    float2* W   = sh;
    float2* stw = sh + Tq;
    const int bg = blockIdx.x >> 2;
    const int p  = blockIdx.x & 3;
    const int u  = threadIdx.x;

    stw[swt(u)] = g_tw[u];
    const float2* Xg = g_spec + (size_t)bg * Tq;
    const float2* fp = g_filt2 + p * Tq;

    // stage 0 (h=1): load spectrum + filter straight from global
    {
        float2 x[8];
        #pragma unroll
        for (int c = 0; c < 8; c++) {
            int e = 8*u + c;
            float2 xs = Xg[swb(e)];
            float2 f  = fp[e];
            x[c] = make_float2(xs.x*f.x - xs.y*f.y, xs.x*f.y + xs.y*f.x);
        }
        dft8_inv(x);
        #pragma unroll
        for (int c = 0; c < 8; c++) W[swb(8*u + c)] = x[c];
        __syncthreads();
    }

    // stages 1,2: shared memory
    #pragma unroll
    for (int s = 1; s < 3; s++) {
        const int h  = 1 << (3*s);       // 8, 64
        const int tm = 512 >> (3*s);
        int j = u & (h - 1);
        int i = ((u ^ j) << 3) | j;
        float2 x[8];
        #pragma unroll
        for (int c = 0; c < 8; c++) x[c] = W[swb(i + c*h)];
        int m = j * tm;
        float2 w1 = stw[swt(m)];
        float2 w2 = cmul(w1, w1), w3 = cmul(w2, w1), w4 = cmul(w2, w2);
        float2 w5 = cmul(w3, w2), w6 = cmul(w3, w3), w7 = cmul(w4, w3);
        x[1] = cmulc(x[1], w1); x[2] = cmulc(x[2], w2); x[3] = cmulc(x[3], w3);
        x[4] = cmulc(x[4], w4); x[5] = cmulc(x[5], w5); x[6] = cmulc(x[6], w6);
        x[7] = cmulc(x[7], w7);
        dft8_inv(x);
        #pragma unroll
        for (int c = 0; c < 8; c++) W[swb(i + c*h)] = x[c];
        __syncthreads();
    }

    // stage 3 (h=512): smem -> regs -> coalesced global stores
    {
        float2 x[8];
        #pragma unroll
        for (int c = 0; c < 8; c++) x[c] = W[swb(u + c*512)];
        float2 w1 = stw[swt(u)];
        float2 w2 = cmul(w1, w1), w3 = cmul(w2, w1), w4 = cmul(w2, w2);
        float2 w5 = cmul(w3, w2), w6 = cmul(w3, w3), w7 = cmul(w4, w3);
        x[1] = cmulc(x[1], w1); x[2] = cmulc(x[2], w2); x[3] = cmulc(x[3], w3);
        x[4] = cmulc(x[4], w4); x[5] = cmulc(x[5], w5); x[6] = cmulc(x[6], w6);
        x[7] = cmulc(x[7], w7);
        dft8_inv(x);
        float* mo0 = g_modes + ((size_t)bg * Kq + 2*p)     * Tq;
        float* mo1 = g_modes + ((size_t)bg * Kq + 2*p + 1) * Tq;
        #pragma unroll
        for (int c = 0; c < 8; c++) {
            mo0[u + 512*c] = x[c].x;
            mo1[u + 512*c] = x[c].y;
        }
    }
}

// ---------------- kernel T: tmptm, one block per bg; early PDL trigger for momfinal overlap ----------------
__global__ void __launch_bounds__(512, 4) tmptm_kernel(float* __restrict__ out) {
    cudaGridDependencySynchronize();             // wait for ifft_kernel completion
    cudaTriggerProgrammaticLaunchCompletion();   // let momfinal launch & run concurrently
    __shared__ int hist[8*HSTRIDE];
    __shared__ int lut[64];
    const int bg  = blockIdx.x;
    const int tid = threadIdx.x;
    for (int i = tid; i < 8*HSTRIDE; i += 512) hist[i] = 0;
    if (tid < 64) lut[tid] = g_lut[tid];
    __syncthreads();

    int* myhist = hist + (tid & 7) * HSTRIDE;
    const int n0 = tid * 8;

    for (int k = 0; k < Kq; k++) {
        const float4* r4 = (const float4*)(g_modes + ((size_t)bg * Kq + k) * Tq + n0);
        float4 a = r4[0], b = r4[1], c = r4[2];
        // key layout: bit0=b01, bit1=b12, bit2=b23, bit3=b02, bit4=b13, bit5=b03
        int key = (a.x>a.y) | ((a.y>a.z)<<1) | ((a.z>a.w)<<2)
                | ((a.x>a.z)<<3) | ((a.y>a.w)<<4) | ((a.x>a.w)<<5);
        int prev = lut[key];
        float w1 = a.y, w2 = a.z, w3 = a.w;
        int lastLin = -1, cnt = 0;
        #define STEP(v, ii) { \
            key = ((key>>1) & 11) | ((w3>(v))<<2) | ((w2>(v))<<4) | ((w1>(v))<<5); \
            int cur = lut[key]; \
            if ((n0 + (ii)) < NPAIR) { \
                int lin = prev*MPq + cur; \
                if (lin == lastLin) cnt++; \
                else { if (cnt) atomicAdd(&myhist[lastLin], cnt); lastLin = lin; cnt = 1; } \
            } \
            prev = cur; w1 = w2; w2 = w3; w3 = (v); }
        STEP(b.x, 0) STEP(b.y, 1) STEP(b.z, 2) STEP(b.w, 3)
        STEP(c.x, 4) STEP(c.y, 5) STEP(c.z, 6) STEP(c.w, 7)
        #undef STEP
        if (cnt) atomicAdd(&myhist[lastLin], cnt);
    }
    __syncthreads();

    const float invs = 1.0f / (float)(Kq * NPAIR);
    for (int i = tid; i < BINS; i += 512) {
        int s = 0;
        #pragma unroll
        for (int c = 0; c < 8; c++) s += hist[c*HSTRIDE + i];
        out[(size_t)bg * BINS + i] = (float)s * invs;
    }
}

// ---------------- kernel M: moments + fmptm (runs concurrently with tmptm) ----------------
__global__ void __launch_bounds__(256) momfinal_kernel(float* __restrict__ out) {
    cudaGridDependencySynchronize();   // PDL: waits only for tmptm's early trigger (ifft already complete)
    const int bg = blockIdx.x, tid = threadIdx.x;
    const float4* base = (const float4*)(g_modes + (size_t)bg * Kq * Tq);
    float s1[Kq]; float s2[36];
    #pragma unroll
    for (int i = 0; i < Kq; i++) s1[i] = 0.0f;
    #pragma unroll
    for (int i = 0; i < 36; i++) s2[i] = 0.0f;

    #pragma unroll
    for (int it = 0; it < 4; it++) {
        const int idx4 = it * 256 + tid;
        float4 E[Kq];
        #pragma unroll
        for (int k = 0; k < Kq; k++) {
            float4 v = base[k * (Tq/4) + idx4];
            E[k] = make_float4(v.x*v.x, v.y*v.y, v.z*v.z, v.w*v.w);
        }
        #pragma unroll
        for (int k = 0; k < Kq; k++) s1[k] += E[k].x + E[k].y + E[k].z + E[k].w;
        int idx = 0;
        #pragma unroll
        for (int k = 0; k < Kq; k++)
            #pragma unroll
            for (int l = k; l < Kq; l++)
                s2[idx++] += E[k].x*E[l].x + E[k].y*E[l].y + E[k].z*E[l].z + E[k].w*E[l].w;
    }

    __shared__ float red[44];
    if (tid < 44) red[tid] = 0.0f;
    __syncthreads();
    #pragma unroll
    for (int i = 0; i < Kq; i++) {
        float v = s1[i];
        #pragma unroll
        for (int o = 16; o; o >>= 1) v += __shfl_down_sync(0xffffffffu, v, o);
        if ((tid & 31) == 0) atomicAdd(&red[i], v);
    }
    #pragma unroll
    for (int i = 0; i < 36; i++) {
        float v = s2[i];
        #pragma unroll
        for (int o = 16; o; o >>= 1) v += __shfl_down_sync(0xffffffffu, v, o);
        if ((tid & 31) == 0) atomicAdd(&red[8 + i], v);
    }
    __syncthreads();

    if (tid < 28) {
        float* out2 = out + (size_t)BG * BINS;
        int k = 0, rem = tid;
        while (rem >= 7 - k) { rem -= 7 - k; k++; }
        int l = k + 1 + rem;
        float S1k = red[k], S1l = red[l];
        int dk = 8 + (k * (17 - k)) / 2;
        int dl = 8 + (l * (17 - l)) / 2;
        float S2kk = red[dk], S2ll = red[dl];
        int off = k * 8 - (k * (k - 1)) / 2 + (l - k);
        float S2kl = red[8 + off];
        const float Tf = (float)Tq;
        float vk = (S2kk - S1k * S1k / Tf) / (Tf - 1.0f);
        float vl = (S2ll - S1l * S1l / Tf) / (Tf - 1.0f);
        float sk = fmaxf(sqrtf(fmaxf(vk, 0.0f)), 1e-8f);
        float sl = fmaxf(sqrtf(fmaxf(vl, 0.0f)), 1e-8f);
        float corr = (S2kl - S1k * S1l / Tf) / (Tf * sk * sl);
        out2[(size_t)bg * 28 + tid] = corr;
    }
}

// ---------------- launch (PDL chaining) ----------------
template <typename... Args, typename F>
static inline void launch_pdl(F func, dim3 grid, dim3 block, size_t smem, Args... args) {
    cudaLaunchConfig_t cfg = {};
    cfg.gridDim = grid;
    cfg.blockDim = block;
    cfg.dynamicSmemBytes = smem;
    cfg.stream = 0;
    cudaLaunchAttribute attr[1];
    attr[0].id = cudaLaunchAttributeProgrammaticStreamSerialization;
    attr[0].val.programmaticStreamSerializationAllowed = 1;
    cfg.attrs = attr;
    cfg.numAttrs = 1;
    cudaLaunchKernelEx(&cfg, func, args...);
}

extern "C" void kernel_launch(void* const* d_in, const int* in_sizes, int n_in,
                              void* d_out, int out_size) {
    const float* hs = (const float*)d_in[0];
    float* out = (float*)d_out;

    cudaFuncSetAttribute(fwd_kernel,  cudaFuncAttributeMaxDynamicSharedMemorySize, DSM);
    cudaFuncSetAttribute(ifft_kernel, cudaFuncAttributeMaxDynamicSharedMemorySize, DSM);

    pool_kernel<<<Bq*64 + 16, 256>>>(hs);
    launch_pdl(fwd_kernel,      dim3(BG),   dim3(512), (size_t)DSM);
    launch_pdl(ifft_kernel,     dim3(BG*4), dim3(512), (size_t)DSM);
    launch_pdl(tmptm_kernel,    dim3(BG),   dim3(512), (size_t)0, out);
    launch_pdl(momfinal_kernel, dim3(BG),   dim3(256), (size_t)0, out);
}

// round 16
// speedup vs baseline: 1.1664x; 1.0619x over previous
#include <cuda_runtime.h>
#include <math.h>

#define Bq 16
#define Gq 32
#define Tq 4096
#define Dq 512
#define Kq 8
#define BG (Bq*Gq)          // 512
#define NWIN (Tq-3)         // 4093
#define NPAIR (NWIN-1)      // 4092
#define MPq 24
#define BINS 576
#define HSTRIDE 577         // bank-staggered histogram copy stride

// ---------------- tables + scratch ----------------
__device__ float2 g_filt2[4*Tq];              // packed filter pairs, base-8 digit-reversed, /4096 folded
__device__ float2 g_tw[512];                  // exp(-2*pi*i*m/4096), m<512
__device__ int    g_lut[64];
__device__ float  g_pooled[(size_t)BG*Tq];    // 8 MB
__device__ float2 g_spec[(size_t)BG*Tq];      // 16 MB spectrum (plain digit-reversed order)
__device__ float  g_modes[(size_t)BG*Kq*Tq + 16]; // 64 MB modes

// ---------------- helpers ----------------
__device__ __forceinline__ int swb(int e){ return e ^ ((e >> 4) & 7) ^ (((e >> 6) & 1) << 3); }
__device__ __forceinline__ int swt(int m){ return m ^ ((m >> 4) & 15); }
__device__ __forceinline__ float2 cadd(float2 a, float2 b){ return make_float2(a.x+b.x, a.y+b.y); }
__device__ __forceinline__ float2 csub(float2 a, float2 b){ return make_float2(a.x-b.x, a.y-b.y); }
__device__ __forceinline__ float2 cmul(float2 a, float2 b){ return make_float2(a.x*b.x - a.y*b.y, a.x*b.y + a.y*b.x); }
__device__ __forceinline__ float2 cmulc(float2 a, float2 b){ return make_float2(a.x*b.x + a.y*b.y, a.y*b.x - a.x*b.y); }

#define CSQ2 0.70710678118654752440f

__device__ __forceinline__ void dft8_fwd(float2* x) {
    float2 t0 = cadd(x[0], x[4]), t1 = csub(x[0], x[4]);
    float2 t2 = cadd(x[2], x[6]), t3 = csub(x[2], x[6]);
    float2 s0 = cadd(x[1], x[5]), s1 = csub(x[1], x[5]);
    float2 s2 = cadd(x[3], x[7]), s3 = csub(x[3], x[7]);
    float2 E0 = cadd(t0, t2), E2 = csub(t0, t2);
    float2 E1 = make_float2(t1.x + t3.y, t1.y - t3.x);
    float2 E3 = make_float2(t1.x - t3.y, t1.y + t3.x);
    float2 O0 = cadd(s0, s2), Oq = csub(s0, s2);
    float2 O1 = make_float2(s1.x + s3.y, s1.y - s3.x);
    float2 O3 = make_float2(s1.x - s3.y, s1.y + s3.x);
    float2 u1 = make_float2(CSQ2*(O1.x + O1.y), CSQ2*(O1.y - O1.x));
    float2 u2 = make_float2(Oq.y, -Oq.x);
    float2 u3 = make_float2(CSQ2*(O3.y - O3.x), -CSQ2*(O3.x + O3.y));
    x[0] = cadd(E0, O0); x[4] = csub(E0, O0);
    x[1] = cadd(E1, u1); x[5] = csub(E1, u1);
    x[2] = cadd(E2, u2); x[6] = csub(E2, u2);
    x[3] = cadd(E3, u3); x[7] = csub(E3, u3);
}

__device__ __forceinline__ void dft8_inv(float2* x) {
    float2 t0 = cadd(x[0], x[4]), t1 = csub(x[0], x[4]);
    float2 t2 = cadd(x[2], x[6]), t3 = csub(x[2], x[6]);
    float2 s0 = cadd(x[1], x[5]), s1 = csub(x[1], x[5]);
    float2 s2 = cadd(x[3], x[7]), s3 = csub(x[3], x[7]);
    float2 E0 = cadd(t0, t2), E2 = csub(t0, t2);
    float2 E1 = make_float2(t1.x - t3.y, t1.y + t3.x);
    float2 E3 = make_float2(t1.x + t3.y, t1.y - t3.x);
    float2 O0 = cadd(s0, s2), Oq = csub(s0, s2);
    float2 O1 = make_float2(s1.x - s3.y, s1.y + s3.x);
    float2 O3 = make_float2(s1.x + s3.y, s1.y - s3.x);
    float2 u1 = make_float2(CSQ2*(O1.x - O1.y), CSQ2*(O1.x + O1.y));
    float2 u2 = make_float2(-Oq.y, Oq.x);
    float2 u3 = make_float2(-CSQ2*(O3.x + O3.y), CSQ2*(O3.x - O3.y));
    x[0] = cadd(E0, O0); x[4] = csub(E0, O0);
    x[1] = cadd(E1, u1); x[5] = csub(E1, u1);
    x[2] = cadd(E2, u2); x[6] = csub(E2, u2);
    x[3] = cadd(E3, u3); x[7] = csub(E3, u3);
}

// ---------------- init work (device function, run by first 16 blocks of pool launch) ----------------
__device__ double filt_val(int idx, double cf) {
    double fr = (idx < Tq/2) ? (double)idx / Tq : (double)(idx - Tq) / Tq;
    double d = fabs(fr - cf) / 0.125;
    return exp(-0.5 * d * d);
}

__device__ void init_work(int blk, int tid) {
    int j = blk * 256 + tid;                 // 0..4095
    if (j < 512) {
        float a = -(float)j / 2048.0f;
        g_tw[j] = make_float2(cospif(a), sinpif(a));
    }
    {
        int f = ((j & 7) << 9) | (((j >> 3) & 7) << 6) | (((j >> 6) & 7) << 3) | ((j >> 9) & 7);
        int fc = (Tq - f) & (Tq - 1);
        #pragma unroll
        for (int p = 0; p < 4; p++) {
            double cf0 = -0.5 + (double)(2*p)   / 7.0;
            double cf1 = -0.5 + (double)(2*p+1) / 7.0;
            double g0 = 0.5 * (filt_val(f, cf0) + filt_val(fc, cf0)) / (double)Tq;
            double g1 = 0.5 * (filt_val(f, cf1) + filt_val(fc, cf1)) / (double)Tq;
            g_filt2[p*Tq + j] = make_float2((float)g0, (float)g1);
        }
    }
    if (j == 0) {
        for (int q = 0; q < 64; q++) g_lut[q] = 0;
        for (int r0 = 0; r0 < 4; r0++)
        for (int r1 = 0; r1 < 4; r1++) { if (r1 == r0) continue;
        for (int r2 = 0; r2 < 4; r2++) { if (r2 == r0 || r2 == r1) continue;
            int r3 = 6 - r0 - r1 - r2;
            int rk[4] = {r0, r1, r2, r3};
            int si[4];
            for (int i = 0; i < 4; i++) si[rk[i]] = i;
            // key layout: bit0=b01, bit1=b12, bit2=b23, bit3=b02, bit4=b13, bit5=b03
            int key = (rk[0]>rk[1]) | ((rk[1]>rk[2])<<1) | ((rk[2]>rk[3])<<2)
                    | ((rk[0]>rk[2])<<3) | ((rk[1]>rk[3])<<4) | ((rk[0]>rk[3])<<5);
            int c0 = (si[0]>si[1]) + (si[0]>si[2]) + (si[0]>si[3]);
            int c1 = (si[1]>si[2]) + (si[1]>si[3]);
            int c2 = (si[2]>si[3]);
            g_lut[key] = 6*c0 + 2*c1 + c2;
        }}
    }
}

// ---------------- kernel P: init blocks + coalesced pooling ----------------
__global__ void __launch_bounds__(256) pool_kernel(const float* __restrict__ hs) {
    if (blockIdx.x < 16) { init_work(blockIdx.x, threadIdx.x); return; }
    __shared__ float sm[64][33];
    const int bid = blockIdx.x - 16;
    const int b  = bid >> 6;
    const int t0 = (bid & 63) * 64;
    const int wid = threadIdx.x >> 5, lane = threadIdx.x & 31;
    #pragma unroll
    for (int rr = 0; rr < 8; rr++) {
        int tr = wid * 8 + rr;
        const float4* row = (const float4*)(hs + ((size_t)b * Tq + t0 + tr) * Dq);
        #pragma unroll
        for (int pass = 0; pass < 4; pass++) {
            float4 v = row[pass*32 + lane];
            float s = v.x + v.y + v.z + v.w;
            s += __shfl_xor_sync(0xffffffffu, s, 1);
            s += __shfl_xor_sync(0xffffffffu, s, 2);
            if ((lane & 3) == 0) sm[tr][pass*8 + (lane >> 2)] = s * (1.0f/16.0f);
        }
    }
    __syncthreads();
    for (int i = threadIdx.x; i < 32*64; i += 256) {
        int g = i >> 6, tr = i & 63;
        g_pooled[((size_t)b * Gq + g) * Tq + t0 + tr] = sm[tr][g];
    }
}

#define DSM ((Tq + 512) * 8)   // buf 4096 float2 + stw 512 float2 = 36 KB

// ---------------- kernel A: forward radix-8 FFT, global->regs->smem->...->global ----------------
__global__ void __launch_bounds__(512, 3) fwd_kernel() {
    cudaGridDependencySynchronize();   // PDL: wait for pool_kernel completion
    extern __shared__ float2 sh[];
    float2* buf = sh;
    float2* stw = sh + Tq;
    const int u = threadIdx.x;
    const int bg = blockIdx.x;

    stw[swt(u)] = g_tw[u];
    const float* pooled = g_pooled + (size_t)bg * Tq;

    // stage 0 (h=512): coalesced global loads straight into registers
    {
        float2 x[8];
        #pragma unroll
        for (int c = 0; c < 8; c++) x[c] = make_float2(pooled[u + 512*c], 0.0f);
        dft8_fwd(x);
        float2 w1 = stw[swt(u)];
        float2 w2 = cmul(w1, w1), w3 = cmul(w2, w1), w4 = cmul(w2, w2);
        float2 w5 = cmul(w3, w2), w6 = cmul(w3, w3), w7 = cmul(w4, w3);
        x[1] = cmul(x[1], w1); x[2] = cmul(x[2], w2); x[3] = cmul(x[3], w3);
        x[4] = cmul(x[4], w4); x[5] = cmul(x[5], w5); x[6] = cmul(x[6], w6);
        x[7] = cmul(x[7], w7);
        #pragma unroll
        for (int c = 0; c < 8; c++) buf[swb(u + 512*c)] = x[c];
        __syncthreads();
    }

    // stages 1,2: shared memory
    #pragma unroll
    for (int s = 1; s < 3; s++) {
        const int h  = 512 >> (3*s);     // 64, 8
        const int tm = 1 << (3*s);
        int j = u & (h - 1);
        int i = ((u ^ j) << 3) | j;
        float2 x[8];
        #pragma unroll
        for (int c = 0; c < 8; c++) x[c] = buf[swb(i + c*h)];
        dft8_fwd(x);
        int m = j * tm;
        float2 w1 = stw[swt(m)];
        float2 w2 = cmul(w1, w1), w3 = cmul(w2, w1), w4 = cmul(w2, w2);
        float2 w5 = cmul(w3, w2), w6 = cmul(w3, w3), w7 = cmul(w4, w3);
        x[1] = cmul(x[1], w1); x[2] = cmul(x[2], w2); x[3] = cmul(x[3], w3);
        x[4] = cmul(x[4], w4); x[5] = cmul(x[5], w5); x[6] = cmul(x[6], w6);
        x[7] = cmul(x[7], w7);
        #pragma unroll
        for (int c = 0; c < 8; c++) buf[swb(i + c*h)] = x[c];
        __syncthreads();
    }

    // stage 3 (h=1): smem -> regs -> PLAIN digit-reversed global store (4x STG.128)
    {
        float2 x[8];
        #pragma unroll
        for (int c = 0; c < 8; c++) x[c] = buf[swb(8*u + c)];
        dft8_fwd(x);
        float4* dst = (float4*)(g_spec + (size_t)bg * Tq + 8*u);
        #pragma unroll
        for (int c2 = 0; c2 < 4; c2++)
            dst[c2] = make_float4(x[2*c2].x, x[2*c2].y, x[2*c2+1].x, x[2*c2+1].y);
    }
}

// ---------------- kernel B: filter (fused, vectorized) + inverse FFT -> g_modes ----------------
__global__ void __launch_bounds__(512, 3) ifft_kernel() {
    cudaGridDependencySynchronize();   // PDL: wait for fwd_kernel completion
    extern __shared__ float2 sh[];
    float2* W   = sh;
    float2* stw = sh + Tq;
    const int bg = blockIdx.x >> 2;
    const int p  = blockIdx.x & 3;
    const int u  = threadIdx.x;

    stw[swt(u)] = g_tw[u];
    const float4* Xg4 = (const float4*)(g_spec  + (size_t)bg * Tq + 8*u);
    const float4* fp4 = (const float4*)(g_filt2 + (size_t)p  * Tq + 8*u);

    // stage 0 (h=1): vectorized spectrum + filter loads, filter in registers
    {
        float2 x[8];
        #pragma unroll
        for (int c2 = 0; c2 < 4; c2++) {
            float4 xs = Xg4[c2];
            float4 f  = fp4[c2];
            x[2*c2]   = make_float2(xs.x*f.x - xs.y*f.y, xs.x*f.y + xs.y*f.x);
            x[2*c2+1] = make_float2(xs.z*f.z - xs.w*f.w, xs.z*f.w + xs.w*f.z);
        }
        dft8_inv(x);
        #pragma unroll
        for (int c = 0; c < 8; c++) W[swb(8*u + c)] = x[c];
        __syncthreads();
    }

    // stages 1,2: shared memory
    #pragma unroll
    for (int s = 1; s < 3; s++) {
        const int h  = 1 << (3*s);       // 8, 64
        const int tm = 512 >> (3*s);
        int j = u & (h - 1);
        int i = ((u ^ j) << 3) | j;
        float2 x[8];
        #pragma unroll
        for (int c = 0; c < 8; c++) x[c] = W[swb(i + c*h)];
        int m = j * tm;
        float2 w1 = stw[swt(m)];
        float2 w2 = cmul(w1, w1), w3 = cmul(w2, w1), w4 = cmul(w2, w2);
        float2 w5 = cmul(w3, w2), w6 = cmul(w3, w3), w7 = cmul(w4, w3);
        x[1] = cmulc(x[1], w1); x[2] = cmulc(x[2], w2); x[3] = cmulc(x[3], w3);
        x[4] = cmulc(x[4], w4); x[5] = cmulc(x[5], w5); x[6] = cmulc(x[6], w6);
        x[7] = cmulc(x[7], w7);
        dft8_inv(x);
        #pragma unroll
        for (int c = 0; c < 8; c++) W[swb(i + c*h)] = x[c];
        __syncthreads();
    }

    // stage 3 (h=512): smem -> regs -> coalesced global stores
    {
        float2 x[8];
        #pragma unroll
        for (int c = 0; c < 8; c++) x[c] = W[swb(u + c*512)];
        float2 w1 = stw[swt(u)];
        float2 w2 = cmul(w1, w1), w3 = cmul(w2, w1), w4 = cmul(w2, w2);
        float2 w5 = cmul(w3, w2), w6 = cmul(w3, w3), w7 = cmul(w4, w3);
        x[1] = cmulc(x[1], w1); x[2] = cmulc(x[2], w2); x[3] = cmulc(x[3], w3);
        x[4] = cmulc(x[4], w4); x[5] = cmulc(x[5], w5); x[6] = cmulc(x[6], w6);
        x[7] = cmulc(x[7], w7);
        dft8_inv(x);
        float* mo0 = g_modes + ((size_t)bg * Kq + 2*p)     * Tq;
        float* mo1 = g_modes + ((size_t)bg * Kq + 2*p + 1) * Tq;
        #pragma unroll
        for (int c = 0; c < 8; c++) {
            mo0[u + 512*c] = x[c].x;
            mo1[u + 512*c] = x[c].y;
        }
    }
}

// ---------------- kernel T: tmptm, one block per bg, direct normalized output ----------------
__global__ void __launch_bounds__(512, 4) tmptm_kernel(float* __restrict__ out) {
    cudaGridDependencySynchronize();   // PDL: wait for ifft_kernel completion
    __shared__ int hist[8*HSTRIDE];
    __shared__ int lut[64];
    const int bg  = blockIdx.x;
    const int tid = threadIdx.x;
    for (int i = tid; i < 8*HSTRIDE; i += 512) hist[i] = 0;
    if (tid < 64) lut[tid] = g_lut[tid];
    __syncthreads();

    int* myhist = hist + (tid & 7) * HSTRIDE;
    const int n0 = tid * 8;

    for (int k = 0; k < Kq; k++) {
        const float4* r4 = (const float4*)(g_modes + ((size_t)bg * Kq + k) * Tq + n0);
        float4 a = r4[0], b = r4[1], c = r4[2];
        // key layout: bit0=b01, bit1=b12, bit2=b23, bit3=b02, bit4=b13, bit5=b03
        int key = (a.x>a.y) | ((a.y>a.z)<<1) | ((a.z>a.w)<<2)
                | ((a.x>a.z)<<3) | ((a.y>a.w)<<4) | ((a.x>a.w)<<5);
        int prev = lut[key];
        float w1 = a.y, w2 = a.z, w3 = a.w;
        int lastLin = -1, cnt = 0;
        #define STEP(v, ii) { \
            key = ((key>>1) & 11) | ((w3>(v))<<2) | ((w2>(v))<<4) | ((w1>(v))<<5); \
            int cur = lut[key]; \
            if ((n0 + (ii)) < NPAIR) { \
                int lin = prev*MPq + cur; \
                if (lin == lastLin) cnt++; \
                else { if (cnt) atomicAdd(&myhist[lastLin], cnt); lastLin = lin; cnt = 1; } \
            } \
            prev = cur; w1 = w2; w2 = w3; w3 = (v); }
        STEP(b.x, 0) STEP(b.y, 1) STEP(b.z, 2) STEP(b.w, 3)
        STEP(c.x, 4) STEP(c.y, 5) STEP(c.z, 6) STEP(c.w, 7)
        #undef STEP
        if (cnt) atomicAdd(&myhist[lastLin], cnt);
    }
    __syncthreads();

    const float invs = 1.0f / (float)(Kq * NPAIR);
    for (int i = tid; i < BINS; i += 512) {
        int s = 0;
        #pragma unroll
        for (int c = 0; c < 8; c++) s += hist[c*HSTRIDE + i];
        out[(size_t)bg * BINS + i] = (float)s * invs;
    }
}

// ---------------- kernel M: moments + fmptm ----------------
__global__ void __launch_bounds__(256) momfinal_kernel(float* __restrict__ out) {
    cudaGridDependencySynchronize();   // PDL: wait for tmptm_kernel completion
    const int bg = blockIdx.x, tid = threadIdx.x;
    const float4* base = (const float4*)(g_modes + (size_t)bg * Kq * Tq);
    float s1[Kq]; float s2[36];
    #pragma unroll
    for (int i = 0; i < Kq; i++) s1[i] = 0.0f;
    #pragma unroll
    for (int i = 0; i < 36; i++) s2[i] = 0.0f;

    #pragma unroll
    for (int it = 0; it < 4; it++) {
        const int idx4 = it * 256 + tid;
        float4 E[Kq];
        #pragma unroll
        for (int k = 0; k < Kq; k++) {
            float4 v = base[k * (Tq/4) + idx4];
            E[k] = make_float4(v.x*v.x, v.y*v.y, v.z*v.z, v.w*v.w);
        }
        #pragma unroll
        for (int k = 0; k < Kq; k++) s1[k] += E[k].x + E[k].y + E[k].z + E[k].w;
        int idx = 0;
        #pragma unroll
        for (int k = 0; k < Kq; k++)
            #pragma unroll
            for (int l = k; l < Kq; l++)
                s2[idx++] += E[k].x*E[l].x + E[k].y*E[l].y + E[k].z*E[l].z + E[k].w*E[l].w;
    }

    __shared__ float red[44];
    if (tid < 44) red[tid] = 0.0f;
    __syncthreads();
    #pragma unroll
    for (int i = 0; i < Kq; i++) {
        float v = s1[i];
        #pragma unroll
        for (int o = 16; o; o >>= 1) v += __shfl_down_sync(0xffffffffu, v, o);
        if ((tid & 31) == 0) atomicAdd(&red[i], v);
    }
    #pragma unroll
    for (int i = 0; i < 36; i++) {
        float v = s2[i];
        #pragma unroll
        for (int o = 16; o; o >>= 1) v += __shfl_down_sync(0xffffffffu, v, o);
        if ((tid & 31) == 0) atomicAdd(&red[8 + i], v);
    }
    __syncthreads();

    if (tid < 28) {
        float* out2 = out + (size_t)BG * BINS;
        int k = 0, rem = tid;
        while (rem >= 7 - k) { rem -= 7 - k; k++; }
        int l = k + 1 + rem;
        float S1k = red[k], S1l = red[l];
        int dk = 8 + (k * (17 - k)) / 2;
        int dl = 8 + (l * (17 - l)) / 2;
        float S2kk = red[dk], S2ll = red[dl];
        int off = k * 8 - (k * (k - 1)) / 2 + (l - k);
        float S2kl = red[8 + off];
        const float Tf = (float)Tq;
        float vk = (S2kk - S1k * S1k / Tf) / (Tf - 1.0f);
        float vl = (S2ll - S1l * S1l / Tf) / (Tf - 1.0f);
        float sk = fmaxf(sqrtf(fmaxf(vk, 0.0f)), 1e-8f);
        float sl = fmaxf(sqrtf(fmaxf(vl, 0.0f)), 1e-8f);
        float corr = (S2kl - S1k * S1l / Tf) / (Tf * sk * sl);
        out2[(size_t)bg * 28 + tid] = corr;
    }
}

// ---------------- launch (PDL chaining) ----------------
template <typename... Args, typename F>
static inline void launch_pdl(F func, dim3 grid, dim3 block, size_t smem, Args... args) {
    cudaLaunchConfig_t cfg = {};
    cfg.gridDim = grid;
    cfg.blockDim = block;
    cfg.dynamicSmemBytes = smem;
    cfg.stream = 0;
    cudaLaunchAttribute attr[1];
    attr[0].id = cudaLaunchAttributeProgrammaticStreamSerialization;
    attr[0].val.programmaticStreamSerializationAllowed = 1;
    cfg.attrs = attr;
    cfg.numAttrs = 1;
    cudaLaunchKernelEx(&cfg, func, args...);
}

extern "C" void kernel_launch(void* const* d_in, const int* in_sizes, int n_in,
                              void* d_out, int out_size) {
    const float* hs = (const float*)d_in[0];
    float* out = (float*)d_out;

    cudaFuncSetAttribute(fwd_kernel,  cudaFuncAttributeMaxDynamicSharedMemorySize, DSM);
    cudaFuncSetAttribute(ifft_kernel, cudaFuncAttributeMaxDynamicSharedMemorySize, DSM);

    pool_kernel<<<Bq*64 + 16, 256>>>(hs);
    launch_pdl(fwd_kernel,      dim3(BG),   dim3(512), (size_t)DSM);
    launch_pdl(ifft_kernel,     dim3(BG*4), dim3(512), (size_t)DSM);
    launch_pdl(tmptm_kernel,    dim3(BG),   dim3(512), (size_t)0, out);
    launch_pdl(momfinal_kernel, dim3(BG),   dim3(256), (size_t)0, out);
}

// round 17
// speedup vs baseline: 1.1685x; 1.0018x over previous
#include <cuda_runtime.h>
#include <math.h>

#define Bq 16
#define Gq 32
#define Tq 4096
#define Dq 512
#define Kq 8
#define BG (Bq*Gq)          // 512
#define NWIN (Tq-3)         // 4093
#define NPAIR (NWIN-1)      // 4092
#define MPq 24
#define BINS 576
#define HSTRIDE 577         // bank-staggered histogram copy stride

// ---------------- tables + scratch ----------------
__device__ float2 g_filt2[4*Tq];              // packed filter pairs, base-8 digit-reversed, /4096 folded
__device__ float2 g_tw[512];                  // exp(-2*pi*i*m/4096), m<512
__device__ int    g_lut[64];
__device__ float  g_pooled[(size_t)BG*Tq];    // 8 MB
__device__ float2 g_spec[(size_t)BG*Tq];      // 16 MB spectrum (plain digit-reversed order)
__device__ float  g_modes[(size_t)BG*Kq*Tq + 16]; // 64 MB modes

// ---------------- helpers ----------------
__device__ __forceinline__ int swb(int e){ return e ^ ((e >> 4) & 7) ^ (((e >> 6) & 1) << 3); }
__device__ __forceinline__ int swt(int m){ return m ^ ((m >> 4) & 15); }
__device__ __forceinline__ float2 cadd(float2 a, float2 b){ return make_float2(a.x+b.x, a.y+b.y); }
__device__ __forceinline__ float2 csub(float2 a, float2 b){ return make_float2(a.x-b.x, a.y-b.y); }
__device__ __forceinline__ float2 cmul(float2 a, float2 b){ return make_float2(a.x*b.x - a.y*b.y, a.x*b.y + a.y*b.x); }
__device__ __forceinline__ float2 cmulc(float2 a, float2 b){ return make_float2(a.x*b.x + a.y*b.y, a.y*b.x - a.x*b.y); }

#define CSQ2 0.70710678118654752440f

__device__ __forceinline__ void dft8_fwd(float2* x) {
    float2 t0 = cadd(x[0], x[4]), t1 = csub(x[0], x[4]);
    float2 t2 = cadd(x[2], x[6]), t3 = csub(x[2], x[6]);
    float2 s0 = cadd(x[1], x[5]), s1 = csub(x[1], x[5]);
    float2 s2 = cadd(x[3], x[7]), s3 = csub(x[3], x[7]);
    float2 E0 = cadd(t0, t2), E2 = csub(t0, t2);
    float2 E1 = make_float2(t1.x + t3.y, t1.y - t3.x);
    float2 E3 = make_float2(t1.x - t3.y, t1.y + t3.x);
    float2 O0 = cadd(s0, s2), Oq = csub(s0, s2);
    float2 O1 = make_float2(s1.x + s3.y, s1.y - s3.x);
    float2 O3 = make_float2(s1.x - s3.y, s1.y + s3.x);
    float2 u1 = make_float2(CSQ2*(O1.x + O1.y), CSQ2*(O1.y - O1.x));
    float2 u2 = make_float2(Oq.y, -Oq.x);
    float2 u3 = make_float2(CSQ2*(O3.y - O3.x), -CSQ2*(O3.x + O3.y));
    x[0] = cadd(E0, O0); x[4] = csub(E0, O0);
    x[1] = cadd(E1, u1); x[5] = csub(E1, u1);
    x[2] = cadd(E2, u2); x[6] = csub(E2, u2);
    x[3] = cadd(E3, u3); x[7] = csub(E3, u3);
}

__device__ __forceinline__ void dft8_inv(float2* x) {
    float2 t0 = cadd(x[0], x[4]), t1 = csub(x[0], x[4]);
    float2 t2 = cadd(x[2], x[6]), t3 = csub(x[2], x[6]);
    float2 s0 = cadd(x[1], x[5]), s1 = csub(x[1], x[5]);
    float2 s2 = cadd(x[3], x[7]), s3 = csub(x[3], x[7]);
    float2 E0 = cadd(t0, t2), E2 = csub(t0, t2);
    float2 E1 = make_float2(t1.x - t3.y, t1.y + t3.x);
    float2 E3 = make_float2(t1.x + t3.y, t1.y - t3.x);
    float2 O0 = cadd(s0, s2), Oq = csub(s0, s2);
    float2 O1 = make_float2(s1.x - s3.y, s1.y + s3.x);
    float2 O3 = make_float2(s1.x + s3.y, s1.y - s3.x);
    float2 u1 = make_float2(CSQ2*(O1.x - O1.y), CSQ2*(O1.x + O1.y));
    float2 u2 = make_float2(-Oq.y, Oq.x);
    float2 u3 = make_float2(-CSQ2*(O3.x + O3.y), CSQ2*(O3.x - O3.y));
    x[0] = cadd(E0, O0); x[4] = csub(E0, O0);
    x[1] = cadd(E1, u1); x[5] = csub(E1, u1);
    x[2] = cadd(E2, u2); x[6] = csub(E2, u2);
    x[3] = cadd(E3, u3); x[7] = csub(E3, u3);
}

// ---------------- init work (device function, run by first 16 blocks of pool launch) ----------------
__device__ double filt_val(int idx, double cf) {
    double fr = (idx < Tq/2) ? (double)idx / Tq : (double)(idx - Tq) / Tq;
    double d = fabs(fr - cf) / 0.125;
    return exp(-0.5 * d * d);
}

__device__ void init_work(int blk, int tid) {
    int j = blk * 256 + tid;                 // 0..4095
    if (j < 512) {
        float a = -(float)j / 2048.0f;
        g_tw[j] = make_float2(cospif(a), sinpif(a));
    }
    {
        int f = ((j & 7) << 9) | (((j >> 3) & 7) << 6) | (((j >> 6) & 7) << 3) | ((j >> 9) & 7);
        int fc = (Tq - f) & (Tq - 1);
        #pragma unroll
        for (int p = 0; p < 4; p++) {
            double cf0 = -0.5 + (double)(2*p)   / 7.0;
            double cf1 = -0.5 + (double)(2*p+1) / 7.0;
            double g0 = 0.5 * (filt_val(f, cf0) + filt_val(fc, cf0)) / (double)Tq;
            double g1 = 0.5 * (filt_val(f, cf1) + filt_val(fc, cf1)) / (double)Tq;
            g_filt2[p*Tq + j] = make_float2((float)g0, (float)g1);
        }
    }
    if (j == 0) {
        for (int q = 0; q < 64; q++) g_lut[q] = 0;
        for (int r0 = 0; r0 < 4; r0++)
        for (int r1 = 0; r1 < 4; r1++) { if (r1 == r0) continue;
        for (int r2 = 0; r2 < 4; r2++) { if (r2 == r0 || r2 == r1) continue;
            int r3 = 6 - r0 - r1 - r2;
            int rk[4] = {r0, r1, r2, r3};
            int si[4];
            for (int i = 0; i < 4; i++) si[rk[i]] = i;
            // key layout: bit0=b01, bit1=b12, bit2=b23, bit3=b02, bit4=b13, bit5=b03
            int key = (rk[0]>rk[1]) | ((rk[1]>rk[2])<<1) | ((rk[2]>rk[3])<<2)
                    | ((rk[0]>rk[2])<<3) | ((rk[1]>rk[3])<<4) | ((rk[0]>rk[3])<<5);
            int c0 = (si[0]>si[1]) + (si[0]>si[2]) + (si[0]>si[3]);
            int c1 = (si[1]>si[2]) + (si[1]>si[3]);
            int c2 = (si[2]>si[3]);
            g_lut[key] = 6*c0 + 2*c1 + c2;
        }}
    }
}

// ---------------- kernel P: init blocks + coalesced pooling ----------------
__global__ void __launch_bounds__(256) pool_kernel(const float* __restrict__ hs) {
    if (blockIdx.x < 16) { init_work(blockIdx.x, threadIdx.x); return; }
    __shared__ float sm[64][33];
    const int bid = blockIdx.x - 16;
    const int b  = bid >> 6;
    const int t0 = (bid & 63) * 64;
    const int wid = threadIdx.x >> 5, lane = threadIdx.x & 31;
    #pragma unroll
    for (int rr = 0; rr < 8; rr++) {
        int tr = wid * 8 + rr;
        const float4* row = (const float4*)(hs + ((size_t)b * Tq + t0 + tr) * Dq);
        #pragma unroll
        for (int pass = 0; pass < 4; pass++) {
            float4 v = row[pass*32 + lane];
            float s = v.x + v.y + v.z + v.w;
            s += __shfl_xor_sync(0xffffffffu, s, 1);
            s += __shfl_xor_sync(0xffffffffu, s, 2);
            if ((lane & 3) == 0) sm[tr][pass*8 + (lane >> 2)] = s * (1.0f/16.0f);
        }
    }
    __syncthreads();
    for (int i = threadIdx.x; i < 32*64; i += 256) {
        int g = i >> 6, tr = i & 63;
        g_pooled[((size_t)b * Gq + g) * Tq + t0 + tr] = sm[tr][g];
    }
}

#define DSM ((Tq + 512) * 8)   // buf 4096 float2 + stw 512 float2 = 36 KB

// ---------------- kernel A: forward radix-8 FFT, global->regs->smem->...->global ----------------
__global__ void __launch_bounds__(512, 3) fwd_kernel() {
    cudaGridDependencySynchronize();   // PDL: wait for pool_kernel completion
    extern __shared__ float2 sh[];
    float2* buf = sh;
    float2* stw = sh + Tq;
    const int u = threadIdx.x;
    const int bg = blockIdx.x;

    stw[swt(u)] = g_tw[u];
    const float* pooled = g_pooled + (size_t)bg * Tq;

    // stage 0 (h=512): coalesced global loads straight into registers
    {
        float2 x[8];
        #pragma unroll
        for (int c = 0; c < 8; c++) x[c] = make_float2(pooled[u + 512*c], 0.0f);
        dft8_fwd(x);
        float2 w1 = stw[swt(u)];
        float2 w2 = cmul(w1, w1), w3 = cmul(w2, w1), w4 = cmul(w2, w2);
        float2 w5 = cmul(w3, w2), w6 = cmul(w3, w3), w7 = cmul(w4, w3);
        x[1] = cmul(x[1], w1); x[2] = cmul(x[2], w2); x[3] = cmul(x[3], w3);
        x[4] = cmul(x[4], w4); x[5] = cmul(x[5], w5); x[6] = cmul(x[6], w6);
        x[7] = cmul(x[7], w7);
        #pragma unroll
        for (int c = 0; c < 8; c++) buf[swb(u + 512*c)] = x[c];
        __syncthreads();
    }

    // stages 1,2: shared memory
    #pragma unroll
    for (int s = 1; s < 3; s++) {
        const int h  = 512 >> (3*s);     // 64, 8
        const int tm = 1 << (3*s);
        int j = u & (h - 1);
        int i = ((u ^ j) << 3) | j;
        float2 x[8];
        #pragma unroll
        for (int c = 0; c < 8; c++) x[c] = buf[swb(i + c*h)];
        dft8_fwd(x);
        int m = j * tm;
        float2 w1 = stw[swt(m)];
        float2 w2 = cmul(w1, w1), w3 = cmul(w2, w1), w4 = cmul(w2, w2);
        float2 w5 = cmul(w3, w2), w6 = cmul(w3, w3), w7 = cmul(w4, w3);
        x[1] = cmul(x[1], w1); x[2] = cmul(x[2], w2); x[3] = cmul(x[3], w3);
        x[4] = cmul(x[4], w4); x[5] = cmul(x[5], w5); x[6] = cmul(x[6], w6);
        x[7] = cmul(x[7], w7);
        #pragma unroll
        for (int c = 0; c < 8; c++) buf[swb(i + c*h)] = x[c];
        __syncthreads();
    }

    // stage 3 (h=1): smem -> regs -> PLAIN digit-reversed global store (4x STG.128)
    {
        float2 x[8];
        #pragma unroll
        for (int c = 0; c < 8; c++) x[c] = buf[swb(8*u + c)];
        dft8_fwd(x);
        float4* dst = (float4*)(g_spec + (size_t)bg * Tq + 8*u);
        #pragma unroll
        for (int c2 = 0; c2 < 4; c2++)
            dst[c2] = make_float4(x[2*c2].x, x[2*c2].y, x[2*c2+1].x, x[2*c2+1].y);
    }
}

// ---------------- kernel B: filter (fused, vectorized) + inverse FFT -> g_modes ----------------
__global__ void __launch_bounds__(512, 3) ifft_kernel() {
    cudaGridDependencySynchronize();   // PDL: wait for fwd_kernel completion
    extern __shared__ float2 sh[];
    float2* W   = sh;
    float2* stw = sh + Tq;
    const int bg = blockIdx.x >> 2;
    const int p  = blockIdx.x & 3;
    const int u  = threadIdx.x;

    stw[swt(u)] = g_tw[u];
    const float4* Xg4 = (const float4*)(g_spec  + (size_t)bg * Tq + 8*u);
    const float4* fp4 = (const float4*)(g_filt2 + (size_t)p  * Tq + 8*u);

    // stage 0 (h=1): vectorized spectrum + filter loads, filter in registers
    {
        float2 x[8];
        #pragma unroll
        for (int c2 = 0; c2 < 4; c2++) {
            float4 xs = Xg4[c2];
            float4 f  = fp4[c2];
            x[2*c2]   = make_float2(xs.x*f.x - xs.y*f.y, xs.x*f.y + xs.y*f.x);
            x[2*c2+1] = make_float2(xs.z*f.z - xs.w*f.w, xs.z*f.w + xs.w*f.z);
        }
        dft8_inv(x);
        #pragma unroll
        for (int c = 0; c < 8; c++) W[swb(8*u + c)] = x[c];
        __syncthreads();
    }

    // stages 1,2: shared memory
    #pragma unroll
    for (int s = 1; s < 3; s++) {
        const int h  = 1 << (3*s);       // 8, 64
        const int tm = 512 >> (3*s);
        int j = u & (h - 1);
        int i = ((u ^ j) << 3) | j;
        float2 x[8];
        #pragma unroll
        for (int c = 0; c < 8; c++) x[c] = W[swb(i + c*h)];
        int m = j * tm;
        float2 w1 = stw[swt(m)];
        float2 w2 = cmul(w1, w1), w3 = cmul(w2, w1), w4 = cmul(w2, w2);
        float2 w5 = cmul(w3, w2), w6 = cmul(w3, w3), w7 = cmul(w4, w3);
        x[1] = cmulc(x[1], w1); x[2] = cmulc(x[2], w2); x[3] = cmulc(x[3], w3);
        x[4] = cmulc(x[4], w4); x[5] = cmulc(x[5], w5); x[6] = cmulc(x[6], w6);
        x[7] = cmulc(x[7], w7);
        dft8_inv(x);
        #pragma unroll
        for (int c = 0; c < 8; c++) W[swb(i + c*h)] = x[c];
        __syncthreads();
    }

    // stage 3 (h=512): smem -> regs -> coalesced global stores
    {
        float2 x[8];
        #pragma unroll
        for (int c = 0; c < 8; c++) x[c] = W[swb(u + c*512)];
        float2 w1 = stw[swt(u)];
        float2 w2 = cmul(w1, w1), w3 = cmul(w2, w1), w4 = cmul(w2, w2);
        float2 w5 = cmul(w3, w2), w6 = cmul(w3, w3), w7 = cmul(w4, w3);
        x[1] = cmulc(x[1], w1); x[2] = cmulc(x[2], w2); x[3] = cmulc(x[3], w3);
        x[4] = cmulc(x[4], w4); x[5] = cmulc(x[5], w5); x[6] = cmulc(x[6], w6);
        x[7] = cmulc(x[7], w7);
        dft8_inv(x);
        float* mo0 = g_modes + ((size_t)bg * Kq + 2*p)     * Tq;
        float* mo1 = g_modes + ((size_t)bg * Kq + 2*p + 1) * Tq;
        #pragma unroll
        for (int c = 0; c < 8; c++) {
            mo0[u + 512*c] = x[c].x;
            mo1[u + 512*c] = x[c].y;
        }
    }
}

// ---------------- kernel T: tmptm at occ 3 (leaves room for momfinal co-residency) ----------------
__global__ void __launch_bounds__(512, 3) tmptm_kernel(float* __restrict__ out) {
    cudaGridDependencySynchronize();             // wait for ifft_kernel completion
    cudaTriggerProgrammaticLaunchCompletion();   // momfinal can launch & co-reside now
    __shared__ int hist[8*HSTRIDE];
    __shared__ int lut[64];
    const int bg  = blockIdx.x;
    const int tid = threadIdx.x;
    for (int i = tid; i < 8*HSTRIDE; i += 512) hist[i] = 0;
    if (tid < 64) lut[tid] = g_lut[tid];
    __syncthreads();

    int* myhist = hist + (tid & 7) * HSTRIDE;
    const int n0 = tid * 8;

    for (int k = 0; k < Kq; k++) {
        const float4* r4 = (const float4*)(g_modes + ((size_t)bg * Kq + k) * Tq + n0);
        float4 a = r4[0], b = r4[1], c = r4[2];
        // key layout: bit0=b01, bit1=b12, bit2=b23, bit3=b02, bit4=b13, bit5=b03
        int key = (a.x>a.y) | ((a.y>a.z)<<1) | ((a.z>a.w)<<2)
                | ((a.x>a.z)<<3) | ((a.y>a.w)<<4) | ((a.x>a.w)<<5);
        int prev = lut[key];
        float w1 = a.y, w2 = a.z, w3 = a.w;
        int lastLin = -1, cnt = 0;
        #define STEP(v, ii) { \
            key = ((key>>1) & 11) | ((w3>(v))<<2) | ((w2>(v))<<4) | ((w1>(v))<<5); \
            int cur = lut[key]; \
            if ((n0 + (ii)) < NPAIR) { \
                int lin = prev*MPq + cur; \
                if (lin == lastLin) cnt++; \
                else { if (cnt) atomicAdd(&myhist[lastLin], cnt); lastLin = lin; cnt = 1; } \
            } \
            prev = cur; w1 = w2; w2 = w3; w3 = (v); }
        STEP(b.x, 0) STEP(b.y, 1) STEP(b.z, 2) STEP(b.w, 3)
        STEP(c.x, 4) STEP(c.y, 5) STEP(c.z, 6) STEP(c.w, 7)
        #undef STEP
        if (cnt) atomicAdd(&myhist[lastLin], cnt);
    }
    __syncthreads();

    const float invs = 1.0f / (float)(Kq * NPAIR);
    for (int i = tid; i < BINS; i += 512) {
        int s = 0;
        #pragma unroll
        for (int c = 0; c < 8; c++) s += hist[c*HSTRIDE + i];
        out[(size_t)bg * BINS + i] = (float)s * invs;
    }
}

// ---------------- kernel M: moments + fmptm (co-resident with tmptm) ----------------
__global__ void __launch_bounds__(256) momfinal_kernel(float* __restrict__ out) {
    cudaGridDependencySynchronize();   // PDL: tmptm's early trigger; g_modes visible since ifft completed
    const int bg = blockIdx.x, tid = threadIdx.x;
    const float4* base = (const float4*)(g_modes + (size_t)bg * Kq * Tq);
    float s1[Kq]; float s2[36];
    #pragma unroll
    for (int i = 0; i < Kq; i++) s1[i] = 0.0f;
    #pragma unroll
    for (int i = 0; i < 36; i++) s2[i] = 0.0f;

    #pragma unroll
    for (int it = 0; it < 4; it++) {
        const int idx4 = it * 256 + tid;
        float4 E[Kq];
        #pragma unroll
        for (int k = 0; k < Kq; k++) {
            float4 v = base[k * (Tq/4) + idx4];
            E[k] = make_float4(v.x*v.x, v.y*v.y, v.z*v.z, v.w*v.w);
        }
        #pragma unroll
        for (int k = 0; k < Kq; k++) s1[k] += E[k].x + E[k].y + E[k].z + E[k].w;
        int idx = 0;
        #pragma unroll
        for (int k = 0; k < Kq; k++)
            #pragma unroll
            for (int l = k; l < Kq; l++)
                s2[idx++] += E[k].x*E[l].x + E[k].y*E[l].y + E[k].z*E[l].z + E[k].w*E[l].w;
    }

    __shared__ float red[44];
    if (tid < 44) red[tid] = 0.0f;
    __syncthreads();
    #pragma unroll
    for (int i = 0; i < Kq; i++) {
        float v = s1[i];
        #pragma unroll
        for (int o = 16; o; o >>= 1) v += __shfl_down_sync(0xffffffffu, v, o);
        if ((tid & 31) == 0) atomicAdd(&red[i], v);
    }
    #pragma unroll
    for (int i = 0; i < 36; i++) {
        float v = s2[i];
        #pragma unroll
        for (int o = 16; o; o >>= 1) v += __shfl_down_sync(0xffffffffu, v, o);
        if ((tid & 31) == 0) atomicAdd(&red[8 + i], v);
    }
    __syncthreads();

    if (tid < 28) {
        float* out2 = out + (size_t)BG * BINS;
        int k = 0, rem = tid;
        while (rem >= 7 - k) { rem -= 7 - k; k++; }
        int l = k + 1 + rem;
        float S1k = red[k], S1l = red[l];
        int dk = 8 + (k * (17 - k)) / 2;
        int dl = 8 + (l * (17 - l)) / 2;
        float S2kk = red[dk], S2ll = red[dl];
        int off = k * 8 - (k * (k - 1)) / 2 + (l - k);
        float S2kl = red[8 + off];
        const float Tf = (float)Tq;
        float vk = (S2kk - S1k * S1k / Tf) / (Tf - 1.0f);
        float vl = (S2ll - S1l * S1l / Tf) / (Tf - 1.0f);
        float sk = fmaxf(sqrtf(fmaxf(vk, 0.0f)), 1e-8f);
        float sl = fmaxf(sqrtf(fmaxf(vl, 0.0f)), 1e-8f);
        float corr = (S2kl - S1k * S1l / Tf) / (Tf * sk * sl);
        out2[(size_t)bg * 28 + tid] = corr;
    }
}

// ---------------- launch (PDL chaining) ----------------
template <typename... Args, typename F>
static inline void launch_pdl(F func, dim3 grid, dim3 block, size_t smem, Args... args) {
    cudaLaunchConfig_t cfg = {};
    cfg.gridDim = grid;
    cfg.blockDim = block;
    cfg.dynamicSmemBytes = smem;
    cfg.stream = 0;
    cudaLaunchAttribute attr[1];
    attr[0].id = cudaLaunchAttributeProgrammaticStreamSerialization;
    attr[0].val.programmaticStreamSerializationAllowed = 1;
    cfg.attrs = attr;
    cfg.numAttrs = 1;
    cudaLaunchKernelEx(&cfg, func, args...);
}

extern "C" void kernel_launch(void* const* d_in, const int* in_sizes, int n_in,
                              void* d_out, int out_size) {
    const float* hs = (const float*)d_in[0];
    float* out = (float*)d_out;

    cudaFuncSetAttribute(fwd_kernel,  cudaFuncAttributeMaxDynamicSharedMemorySize, DSM);
    cudaFuncSetAttribute(ifft_kernel, cudaFuncAttributeMaxDynamicSharedMemorySize, DSM);

    pool_kernel<<<Bq*64 + 16, 256>>>(hs);
    launch_pdl(fwd_kernel,      dim3(BG),   dim3(512), (size_t)DSM);
    launch_pdl(ifft_kernel,     dim3(BG*4), dim3(512), (size_t)DSM);
    launch_pdl(tmptm_kernel,    dim3(BG),   dim3(512), (size_t)0, out);
    launch_pdl(momfinal_kernel, dim3(BG),   dim3(256), (size_t)0, out);
}